// round 1
// baseline (speedup 1.0000x reference)
#include <cuda_runtime.h>
#include <cstdint>

#define SEQ    2048
#define BATCH  4
#define NHEADS 16
#define HDIM   64
#define DM     1024
#define BQ     64
#define BK     64
#define KSTR   68   // smem row stride for K tile (bank = 4g+t, conflict-free)
#define VSTR   72   // smem row stride for V tile (bank = 8t+g, conflict-free)

// Precomputed relative-bias table: [head][distance], distance = max(q-k, 0)
__device__ float g_bias[NHEADS * SEQ];

__global__ void build_bias_kernel(const float* __restrict__ rab) {
    int d = blockIdx.x * blockDim.x + threadIdx.x;
    if (d >= SEQ) return;
    int bkt;
    if (d < 16) {
        bkt = d;
    } else {
        // matches: 16 + int(log(d/16)/log(8) * 16), clamped to 31
        float t = logf((float)d * 0.0625f) / logf(8.0f) * 16.0f;
        bkt = 16 + (int)t;
        if (bkt > 31) bkt = 31;
    }
#pragma unroll
    for (int h = 0; h < NHEADS; ++h)
        g_bias[h * SEQ + d] = rab[bkt * NHEADS + h];
}

__device__ __forceinline__ unsigned f2tf(float x) {
    unsigned r;
    asm("cvt.rna.tf32.f32 %0, %1;" : "=r"(r) : "f"(x));
    return r;
}

__device__ __forceinline__ void mma_tf32(float c[4], const unsigned a[4],
                                         unsigned b0, unsigned b1) {
    asm volatile(
        "mma.sync.aligned.m16n8k8.row.col.f32.tf32.tf32.f32 "
        "{%0,%1,%2,%3}, {%4,%5,%6,%7}, {%8,%9}, {%0,%1,%2,%3};\n"
        : "+f"(c[0]), "+f"(c[1]), "+f"(c[2]), "+f"(c[3])
        : "r"(a[0]), "r"(a[1]), "r"(a[2]), "r"(a[3]), "r"(b0), "r"(b1));
}

__device__ __forceinline__ float silu(float s) {
    return s / (1.0f + __expf(-s));
}

__global__ void __launch_bounds__(128, 3) paa_kernel(
    const float* __restrict__ Q, const float* __restrict__ K,
    const float* __restrict__ V, float* __restrict__ Out)
{
    __shared__ float Ks[BK * KSTR];
    __shared__ float Vs[BK * VSTR];

    const int qt   = blockIdx.x;   // q tile (0..31)
    const int h    = blockIdx.y;   // head
    const int b    = blockIdx.z;   // batch
    const int tid  = threadIdx.x;
    const int warp = tid >> 5;
    const int lane = tid & 31;
    const int g    = lane >> 2;    // group id (row within mma tile)
    const int t    = lane & 3;     // thread in group

    const size_t headoff = (size_t)b * SEQ * DM + (size_t)h * HDIM;
    const float* qp = Q + headoff;
    const float* kp = K + headoff;
    const float* vp = V + headoff;
    const float* biasp = g_bias + h * SEQ;

    const int qrow0 = qt * BQ + warp * 16;  // this warp's first q row

    // Preload Q fragments (tf32), kept in registers for all 32 k-tiles.
    // a0=(g, 8dc+t) a1=(g+8, 8dc+t) a2=(g, 8dc+t+4) a3=(g+8, 8dc+t+4)
    unsigned qa[8][4];
#pragma unroll
    for (int dc = 0; dc < 8; ++dc) {
        int c0 = dc * 8 + t;
        qa[dc][0] = f2tf(qp[(size_t)(qrow0 + g)     * DM + c0]);
        qa[dc][1] = f2tf(qp[(size_t)(qrow0 + g + 8) * DM + c0]);
        qa[dc][2] = f2tf(qp[(size_t)(qrow0 + g)     * DM + c0 + 4]);
        qa[dc][3] = f2tf(qp[(size_t)(qrow0 + g + 8) * DM + c0 + 4]);
    }

    float oacc[8][4];
#pragma unroll
    for (int i = 0; i < 8; ++i)
#pragma unroll
        for (int j = 0; j < 4; ++j) oacc[i][j] = 0.0f;

    for (int kt = 0; kt < SEQ / BK; ++kt) {
        const int k0 = kt * BK;
        __syncthreads();  // previous tile's reads finished
        // Cooperative load of K/V tiles (64x64), tf32-rounded at store time.
#pragma unroll
        for (int i = 0; i < 8; ++i) {
            int idx = tid + i * 128;     // 0..1023
            int row = idx >> 4;
            int cv  = (idx & 15) * 4;
            const float4 kf = *(const float4*)(kp + (size_t)(k0 + row) * DM + cv);
            const float4 vf = *(const float4*)(vp + (size_t)(k0 + row) * DM + cv);
            float4 ko, vo;
            ko.x = __uint_as_float(f2tf(kf.x)); ko.y = __uint_as_float(f2tf(kf.y));
            ko.z = __uint_as_float(f2tf(kf.z)); ko.w = __uint_as_float(f2tf(kf.w));
            vo.x = __uint_as_float(f2tf(vf.x)); vo.y = __uint_as_float(f2tf(vf.y));
            vo.z = __uint_as_float(f2tf(vf.z)); vo.w = __uint_as_float(f2tf(vf.w));
            *(float4*)(Ks + row * KSTR + cv) = ko;
            *(float4*)(Vs + row * VSTR + cv) = vo;
        }
        __syncthreads();

        // ---- S = Q @ K^T  (16 x 64 per warp) ----
        float sacc[8][4];
#pragma unroll
        for (int i = 0; i < 8; ++i)
#pragma unroll
            for (int j = 0; j < 4; ++j) sacc[i][j] = 0.0f;

#pragma unroll
        for (int nc = 0; nc < 8; ++nc) {
            const float* krow = Ks + (nc * 8 + g) * KSTR;
#pragma unroll
            for (int dc = 0; dc < 8; ++dc) {
                unsigned b0 = __float_as_uint(krow[dc * 8 + t]);
                unsigned b1 = __float_as_uint(krow[dc * 8 + t + 4]);
                mma_tf32(sacc[nc], qa[dc], b0, b1);
            }
        }

        // ---- bias + silu + O += P @ V, chunk by chunk over k' ----
#pragma unroll
        for (int kc = 0; kc < 8; ++kc) {
            const int col0 = k0 + kc * 8 + 2 * t;
            const int r0 = qrow0 + g;
            const int r1 = r0 + 8;
            int d00 = r0 - col0;     if (d00 < 0) d00 = 0;
            int d01 = r0 - col0 - 1; if (d01 < 0) d01 = 0;
            int d10 = r1 - col0;     if (d10 < 0) d10 = 0;
            int d11 = r1 - col0 - 1; if (d11 < 0) d11 = 0;
            float s0 = sacc[kc][0] + biasp[d00];
            float s1 = sacc[kc][1] + biasp[d01];
            float s2 = sacc[kc][2] + biasp[d10];
            float s3 = sacc[kc][3] + biasp[d11];
            unsigned u0 = f2tf(silu(s0));
            unsigned u1 = f2tf(silu(s1));
            unsigned u2 = f2tf(silu(s2));
            unsigned u3 = f2tf(silu(s3));

            // Re-layout acc fragment (cols {2t,2t+1}) into A fragment (cols {t,t+4})
            // via intra-quad shuffles.
            const int srcA = (lane & ~3) | (t >> 1);
            const int srcB = srcA + 2;
            unsigned sA0 = __shfl_sync(0xffffffffu, u0, srcA);
            unsigned sA1 = __shfl_sync(0xffffffffu, u1, srcA);
            unsigned sA2 = __shfl_sync(0xffffffffu, u2, srcA);
            unsigned sA3 = __shfl_sync(0xffffffffu, u3, srcA);
            unsigned sB0 = __shfl_sync(0xffffffffu, u0, srcB);
            unsigned sB1 = __shfl_sync(0xffffffffu, u1, srcB);
            unsigned sB2 = __shfl_sync(0xffffffffu, u2, srcB);
            unsigned sB3 = __shfl_sync(0xffffffffu, u3, srcB);
            unsigned af[4];
            af[0] = (t & 1) ? sA1 : sA0;  // (row g,   col t)
            af[1] = (t & 1) ? sA3 : sA2;  // (row g+8, col t)
            af[2] = (t & 1) ? sB1 : sB0;  // (row g,   col t+4)
            af[3] = (t & 1) ? sB3 : sB2;  // (row g+8, col t+4)

#pragma unroll
            for (int nc = 0; nc < 8; ++nc) {
                unsigned b0 = __float_as_uint(Vs[(kc * 8 + t)     * VSTR + nc * 8 + g]);
                unsigned b1 = __float_as_uint(Vs[(kc * 8 + t + 4) * VSTR + nc * 8 + g]);
                mma_tf32(oacc[nc], af, b0, b1);
            }
        }
    }

    // ---- epilogue: O is [16 x 64] per warp, write to [B,S,H*64] ----
    float* op = Out + (size_t)b * SEQ * DM + (size_t)h * HDIM;
#pragma unroll
    for (int nc = 0; nc < 8; ++nc) {
        int c = nc * 8 + 2 * t;
        float2 v01 = make_float2(oacc[nc][0], oacc[nc][1]);
        float2 v23 = make_float2(oacc[nc][2], oacc[nc][3]);
        *(float2*)(op + (size_t)(qrow0 + g)     * DM + c) = v01;
        *(float2*)(op + (size_t)(qrow0 + g + 8) * DM + c) = v23;
    }
}

extern "C" void kernel_launch(void* const* d_in, const int* in_sizes, int n_in,
                              void* d_out, int out_size) {
    // metadata order: v, k, q, rab_weight
    const float* v   = (const float*)d_in[0];
    const float* k   = (const float*)d_in[1];
    const float* q   = (const float*)d_in[2];
    const float* rab = (const float*)d_in[3];
    float* out = (float*)d_out;

    build_bias_kernel<<<SEQ / 256, 256>>>(rab);

    dim3 grid(SEQ / BQ, NHEADS, BATCH);
    paa_kernel<<<grid, 128>>>(q, k, v, out);
}